// round 4
// baseline (speedup 1.0000x reference)
#include <cuda_runtime.h>
#include <cstdint>

static constexpr int NE   = 8;
static constexpr int HID  = 2048;
static constexpr int INTR = 8192;
static constexpr int TOK  = 1024;   // tokens per expert

// intermediate activations h = up * silu(gate): 8*1024*8192 floats = 256 MB
__device__ float g_h[(size_t)NE * TOK * INTR];

// ---------------- PTX helpers ----------------------------------------------------
__device__ __forceinline__ uint32_t s2u(const void* p) {
    return (uint32_t)__cvta_generic_to_shared(p);
}
#define CP16(dst, src) \
    asm volatile("cp.async.cg.shared.global [%0], [%1], 16;" :: "r"(dst), "l"(src) : "memory")
#define CP_COMMIT() asm volatile("cp.async.commit_group;" ::: "memory")
#define CP_WAIT(n)  asm volatile("cp.async.wait_group %0;" :: "n"(n) : "memory")

__device__ __forceinline__ uint32_t f2tf(float f) {   // round-to-nearest tf32 (unbiased)
    uint32_t r;
    asm("cvt.rna.tf32.f32 %0, %1;" : "=r"(r) : "f"(f));
    return r;
}
__device__ __forceinline__ void mma8(float* c, const uint32_t* a, const uint32_t* b) {
    asm volatile(
        "mma.sync.aligned.m16n8k8.row.col.f32.tf32.tf32.f32 "
        "{%0,%1,%2,%3}, {%4,%5,%6,%7}, {%8,%9}, {%0,%1,%2,%3};"
        : "+f"(c[0]), "+f"(c[1]), "+f"(c[2]), "+f"(c[3])
        : "r"(a[0]), "r"(a[1]), "r"(a[2]), "r"(a[3]), "r"(b[0]), "r"(b[1]));
}
__device__ __forceinline__ float silu(float x) {
    return x * (1.0f / (1.0f + __expf(-x)));
}

// ---------------- SMEM geometry ---------------------------------------------------
// A tile: 128 m-rows x 32 k, stride 36 floats (pad 4) -> bank(4m+k) conflict-free
// B tile: 32 k-rows x 128 n, stride 136 floats (pad 8) -> bank(8k+n) conflict-free
static constexpr int A_STRIDE = 36;
static constexpr int B_STRIDE = 136;
static constexpr int A_FLOATS = 128 * A_STRIDE;            // 4608
static constexpr int B_FLOATS = 32 * B_STRIDE;             // 4352

// gemm1: A + Bgate + Bup per stage, 3 stages
static constexpr int G1_STAGE_F = A_FLOATS + 2 * B_FLOATS; // 13312 floats = 53248 B
static constexpr int G1_STAGES  = 3;
static constexpr int G1_SMEM    = G1_STAGE_F * G1_STAGES * 4;  // 159744 B

// gemm2: A + B per stage, 4 stages
static constexpr int G2_STAGE_F = A_FLOATS + B_FLOATS;     // 8960 floats = 35840 B
static constexpr int G2_STAGES  = 4;
static constexpr int G2_SMEM    = G2_STAGE_F * G2_STAGES * 4;  // 143360 B

// load one stage's A tile: 128 x 32 floats = 1024 x 16B, 4 per thread (256 thr)
__device__ __forceinline__ void load_A(uint32_t sbase, const float* __restrict__ g,
                                       int ldk, int tid) {
#pragma unroll
    for (int i = 0; i < 4; i++) {
        int idx = tid + i * 256;
        int r = idx >> 3, c = idx & 7;                      // r: m-row, c: 16B chunk
        CP16(sbase + (uint32_t)(r * A_STRIDE + c * 4) * 4, g + (size_t)r * ldk + c * 4);
    }
}
// load one stage's B tile: 32 k-rows x 128 floats = 1024 x 16B, 4 per thread
__device__ __forceinline__ void load_B(uint32_t sbase, const float* __restrict__ g,
                                       int ldn, int tid) {
#pragma unroll
    for (int i = 0; i < 4; i++) {
        int idx = tid + i * 256;
        int r = idx >> 5, c = idx & 31;                     // r: k-row, c: 16B chunk
        CP16(sbase + (uint32_t)(r * B_STRIDE + c * 4) * 4, g + (size_t)r * ldn + c * 4);
    }
}

// ---------------- GEMM 1: h = up * silu(gate) -------------------------------------
__global__ void __launch_bounds__(256, 1)
gemm_gateup(const float* __restrict__ X, const float* __restrict__ Wg,
            const float* __restrict__ Wu, float* __restrict__ Hout) {
    extern __shared__ float sm[];
    const int tid = threadIdx.x, wid = tid >> 5, lid = tid & 31;
    const int gq = lid >> 2, tg = lid & 3;                  // quad group / thread-in-group
    const int wm = wid >> 2, wn = wid & 3;                  // warps: 2 (m) x 4 (n)
    const int e = blockIdx.z;
    const int m0 = blockIdx.x * 128;
    const int n0 = blockIdx.y * 128;
    const uint32_t sb = s2u(sm);

    const float* gA = X  + ((size_t)e * TOK + m0) * HID;                 // row m, k contig
    const float* gG = Wg + (size_t)e * HID * INTR + n0;                  // row k, n contig
    const float* gU = Wu + (size_t)e * HID * INTR + n0;

    float accg[4][4][4], accu[4][4][4];
#pragma unroll
    for (int i = 0; i < 4; i++)
#pragma unroll
        for (int j = 0; j < 4; j++)
#pragma unroll
            for (int v = 0; v < 4; v++) { accg[i][j][v] = 0.f; accu[i][j][v] = 0.f; }

    const int NT = HID / 32;   // 64
    // prologue: stages 0..S-2
#pragma unroll
    for (int s = 0; s < G1_STAGES - 1; s++) {
        uint32_t base = sb + (uint32_t)(s * G1_STAGE_F) * 4;
        load_A(base, gA + s * 32, HID, tid);
        load_B(base + A_FLOATS * 4,              gG + (size_t)(s * 32) * INTR, INTR, tid);
        load_B(base + (A_FLOATS + B_FLOATS) * 4, gU + (size_t)(s * 32) * INTR, INTR, tid);
        CP_COMMIT();
    }

    for (int kt = 0; kt < NT; kt++) {
        CP_WAIT(G1_STAGES - 2);
        __syncthreads();
        int pf = kt + G1_STAGES - 1;
        if (pf < NT) {
            uint32_t base = sb + (uint32_t)((pf % G1_STAGES) * G1_STAGE_F) * 4;
            load_A(base, gA + pf * 32, HID, tid);
            load_B(base + A_FLOATS * 4,              gG + (size_t)(pf * 32) * INTR, INTR, tid);
            load_B(base + (A_FLOATS + B_FLOATS) * 4, gU + (size_t)(pf * 32) * INTR, INTR, tid);
        }
        CP_COMMIT();

        const float* As = sm + (kt % G1_STAGES) * G1_STAGE_F;
        const float* Bg = As + A_FLOATS;
        const float* Bu = Bg + B_FLOATS;
#pragma unroll
        for (int ks = 0; ks < 4; ks++) {
            const int k0 = ks * 8;
            uint32_t a[4][4];
#pragma unroll
            for (int mt = 0; mt < 4; mt++) {
                int m = wm * 64 + mt * 16 + gq;
                a[mt][0] = f2tf(As[m * A_STRIDE + k0 + tg]);
                a[mt][1] = f2tf(As[(m + 8) * A_STRIDE + k0 + tg]);
                a[mt][2] = f2tf(As[m * A_STRIDE + k0 + tg + 4]);
                a[mt][3] = f2tf(As[(m + 8) * A_STRIDE + k0 + tg + 4]);
            }
            uint32_t bg[4][2], bu[4][2];
#pragma unroll
            for (int nt = 0; nt < 4; nt++) {
                int n = wn * 32 + nt * 8 + gq;
                bg[nt][0] = f2tf(Bg[(k0 + tg) * B_STRIDE + n]);
                bg[nt][1] = f2tf(Bg[(k0 + tg + 4) * B_STRIDE + n]);
                bu[nt][0] = f2tf(Bu[(k0 + tg) * B_STRIDE + n]);
                bu[nt][1] = f2tf(Bu[(k0 + tg + 4) * B_STRIDE + n]);
            }
#pragma unroll
            for (int mt = 0; mt < 4; mt++)
#pragma unroll
                for (int nt = 0; nt < 4; nt++) {
                    mma8(accg[mt][nt], a[mt], bg[nt]);
                    mma8(accu[mt][nt], a[mt], bu[nt]);
                }
        }
    }

    // epilogue: h = up * silu(gate)
    const size_t hb = ((size_t)e * TOK + m0 + wm * 64) * INTR + n0 + wn * 32;
#pragma unroll
    for (int mt = 0; mt < 4; mt++)
#pragma unroll
        for (int nt = 0; nt < 4; nt++) {
            int col = nt * 8 + tg * 2;
            {
                int row = mt * 16 + gq;
                float h0 = accu[mt][nt][0] * silu(accg[mt][nt][0]);
                float h1 = accu[mt][nt][1] * silu(accg[mt][nt][1]);
                *reinterpret_cast<float2*>(&Hout[hb + (size_t)row * INTR + col]) =
                    make_float2(h0, h1);
            }
            {
                int row = mt * 16 + gq + 8;
                float h2 = accu[mt][nt][2] * silu(accg[mt][nt][2]);
                float h3 = accu[mt][nt][3] * silu(accg[mt][nt][3]);
                *reinterpret_cast<float2*>(&Hout[hb + (size_t)row * INTR + col]) =
                    make_float2(h2, h3);
            }
        }
}

// ---------------- GEMM 2: out = h @ down_w ----------------------------------------
__global__ void __launch_bounds__(256, 1)
gemm_down(const float* __restrict__ Hin, const float* __restrict__ Wd,
          float* __restrict__ Out) {
    extern __shared__ float sm[];
    const int tid = threadIdx.x, wid = tid >> 5, lid = tid & 31;
    const int gq = lid >> 2, tg = lid & 3;
    const int wm = wid >> 2, wn = wid & 3;
    const int e = blockIdx.z;
    const int m0 = blockIdx.x * 128;
    const int n0 = blockIdx.y * 128;
    const uint32_t sb = s2u(sm);

    const float* gA = Hin + ((size_t)e * TOK + m0) * INTR;
    const float* gB = Wd  + (size_t)e * INTR * HID + n0;

    float acc[4][4][4];
#pragma unroll
    for (int i = 0; i < 4; i++)
#pragma unroll
        for (int j = 0; j < 4; j++)
#pragma unroll
            for (int v = 0; v < 4; v++) acc[i][j][v] = 0.f;

    const int NT = INTR / 32;   // 256
#pragma unroll
    for (int s = 0; s < G2_STAGES - 1; s++) {
        uint32_t base = sb + (uint32_t)(s * G2_STAGE_F) * 4;
        load_A(base, gA + s * 32, INTR, tid);
        load_B(base + A_FLOATS * 4, gB + (size_t)(s * 32) * HID, HID, tid);
        CP_COMMIT();
    }

    for (int kt = 0; kt < NT; kt++) {
        CP_WAIT(G2_STAGES - 2);
        __syncthreads();
        int pf = kt + G2_STAGES - 1;
        if (pf < NT) {
            uint32_t base = sb + (uint32_t)((pf % G2_STAGES) * G2_STAGE_F) * 4;
            load_A(base, gA + pf * 32, INTR, tid);
            load_B(base + A_FLOATS * 4, gB + (size_t)(pf * 32) * HID, HID, tid);
        }
        CP_COMMIT();

        const float* As = sm + (kt % G2_STAGES) * G2_STAGE_F;
        const float* Bs = As + A_FLOATS;
#pragma unroll
        for (int ks = 0; ks < 4; ks++) {
            const int k0 = ks * 8;
            uint32_t a[4][4];
#pragma unroll
            for (int mt = 0; mt < 4; mt++) {
                int m = wm * 64 + mt * 16 + gq;
                a[mt][0] = f2tf(As[m * A_STRIDE + k0 + tg]);
                a[mt][1] = f2tf(As[(m + 8) * A_STRIDE + k0 + tg]);
                a[mt][2] = f2tf(As[m * A_STRIDE + k0 + tg + 4]);
                a[mt][3] = f2tf(As[(m + 8) * A_STRIDE + k0 + tg + 4]);
            }
            uint32_t b[4][2];
#pragma unroll
            for (int nt = 0; nt < 4; nt++) {
                int n = wn * 32 + nt * 8 + gq;
                b[nt][0] = f2tf(Bs[(k0 + tg) * B_STRIDE + n]);
                b[nt][1] = f2tf(Bs[(k0 + tg + 4) * B_STRIDE + n]);
            }
#pragma unroll
            for (int mt = 0; mt < 4; mt++)
#pragma unroll
                for (int nt = 0; nt < 4; nt++)
                    mma8(acc[mt][nt], a[mt], b[nt]);
        }
    }

    const size_t ob = ((size_t)e * TOK + m0 + wm * 64) * HID + n0 + wn * 32;
#pragma unroll
    for (int mt = 0; mt < 4; mt++)
#pragma unroll
        for (int nt = 0; nt < 4; nt++) {
            int col = nt * 8 + tg * 2;
            int row = mt * 16 + gq;
            *reinterpret_cast<float2*>(&Out[ob + (size_t)row * HID + col]) =
                make_float2(acc[mt][nt][0], acc[mt][nt][1]);
            *reinterpret_cast<float2*>(&Out[ob + (size_t)(row + 8) * HID + col]) =
                make_float2(acc[mt][nt][2], acc[mt][nt][3]);
        }
}

// ---------------- launch ----------------------------------------------------------
extern "C" void kernel_launch(void* const* d_in, const int* in_sizes, int n_in,
                              void* d_out, int out_size) {
    const float* X  = (const float*)d_in[0];
    const float* Wg = (const float*)d_in[1];
    const float* Wu = (const float*)d_in[2];
    const float* Wd = (const float*)d_in[3];
    float* out = (float*)d_out;

    float* hbuf;
    cudaGetSymbolAddress((void**)&hbuf, g_h);

    cudaFuncSetAttribute(gemm_gateup, cudaFuncAttributeMaxDynamicSharedMemorySize, G1_SMEM);
    cudaFuncSetAttribute(gemm_down,   cudaFuncAttributeMaxDynamicSharedMemorySize, G2_SMEM);

    // x = m tiles fastest -> consecutive CTAs share weight strips (L2 reuse)
    gemm_gateup<<<dim3(TOK / 128, INTR / 128, NE), 256, G1_SMEM>>>(X, Wg, Wu, hbuf);
    gemm_down  <<<dim3(TOK / 128, HID / 128, NE), 256, G2_SMEM>>>(hbuf, Wd, out);
}

// round 5
// speedup vs baseline: 1.0381x; 1.0381x over previous
#include <cuda_runtime.h>
#include <cstdint>

static constexpr int NE   = 8;
static constexpr int HID  = 2048;
static constexpr int INTR = 8192;
static constexpr int TOK  = 1024;   // tokens per expert

// intermediate activations h = up * silu(gate): 8*1024*8192 floats = 256 MB
__device__ float g_h[(size_t)NE * TOK * INTR];

// ---------------- PTX helpers ----------------------------------------------------
__device__ __forceinline__ uint32_t s2u(const void* p) {
    return (uint32_t)__cvta_generic_to_shared(p);
}
#define CP16(dst, src) \
    asm volatile("cp.async.cg.shared.global [%0], [%1], 16;" :: "r"(dst), "l"(src) : "memory")
#define CP_COMMIT() asm volatile("cp.async.commit_group;" ::: "memory")
#define CP_WAIT(n)  asm volatile("cp.async.wait_group %0;" :: "n"(n) : "memory")

__device__ __forceinline__ uint32_t f2tf(float f) {   // round-to-nearest tf32 (unbiased)
    uint32_t r;
    asm("cvt.rna.tf32.f32 %0, %1;" : "=r"(r) : "f"(f));
    return r;
}
// NOTE: non-volatile — pure register op; lets ptxas software-pipeline fragment
// loads/cvts of the next k-slice underneath the current MMA block.
__device__ __forceinline__ void mma8(float* c, const uint32_t* a, const uint32_t* b) {
    asm("mma.sync.aligned.m16n8k8.row.col.f32.tf32.tf32.f32 "
        "{%0,%1,%2,%3}, {%4,%5,%6,%7}, {%8,%9}, {%0,%1,%2,%3};"
        : "+f"(c[0]), "+f"(c[1]), "+f"(c[2]), "+f"(c[3])
        : "r"(a[0]), "r"(a[1]), "r"(a[2]), "r"(a[3]), "r"(b[0]), "r"(b[1]));
}
__device__ __forceinline__ float silu(float x) {
    return x * (1.0f / (1.0f + __expf(-x)));
}

// ---------------- SMEM geometry ---------------------------------------------------
// A tile: 128 m-rows x 32 k, stride 36 floats (pad 4) -> bank(4m+k) conflict-free
// B tile: 32 k-rows x 128 n, stride 136 floats (pad 8) -> bank(8k+n) conflict-free
static constexpr int A_STRIDE = 36;
static constexpr int B_STRIDE = 136;
static constexpr int A_FLOATS = 128 * A_STRIDE;            // 4608
static constexpr int B_FLOATS = 32 * B_STRIDE;             // 4352

// gemm1: A + Bgate + Bup per stage, 3 stages, 1 CTA/SM (needs >128 regs)
static constexpr int G1_STAGE_F = A_FLOATS + 2 * B_FLOATS; // 13312 floats = 53248 B
static constexpr int G1_STAGES  = 3;
static constexpr int G1_SMEM    = G1_STAGE_F * G1_STAGES * 4;  // 159744 B

// gemm2: A + B per stage, 3 stages, 2 CTAs/SM (128-reg cap, 2*105KB smem)
static constexpr int G2_STAGE_F = A_FLOATS + B_FLOATS;     // 8960 floats = 35840 B
static constexpr int G2_STAGES  = 3;
static constexpr int G2_SMEM    = G2_STAGE_F * G2_STAGES * 4;  // 107520 B

// load one stage's A tile: 128 x 32 floats = 1024 x 16B, 4 per thread (256 thr)
__device__ __forceinline__ void load_A(uint32_t sbase, const float* __restrict__ g,
                                       int ldk, int tid) {
#pragma unroll
    for (int i = 0; i < 4; i++) {
        int idx = tid + i * 256;
        int r = idx >> 3, c = idx & 7;                      // r: m-row, c: 16B chunk
        CP16(sbase + (uint32_t)(r * A_STRIDE + c * 4) * 4, g + (size_t)r * ldk + c * 4);
    }
}
// load one stage's B tile: 32 k-rows x 128 floats = 1024 x 16B, 4 per thread
__device__ __forceinline__ void load_B(uint32_t sbase, const float* __restrict__ g,
                                       int ldn, int tid) {
#pragma unroll
    for (int i = 0; i < 4; i++) {
        int idx = tid + i * 256;
        int r = idx >> 5, c = idx & 31;                     // r: k-row, c: 16B chunk
        CP16(sbase + (uint32_t)(r * B_STRIDE + c * 4) * 4, g + (size_t)r * ldn + c * 4);
    }
}

// ---------------- GEMM 1: h = up * silu(gate) -------------------------------------
__global__ void __launch_bounds__(256, 1)
gemm_gateup(const float* __restrict__ X, const float* __restrict__ Wg,
            const float* __restrict__ Wu, float* __restrict__ Hout) {
    extern __shared__ float sm[];
    const int tid = threadIdx.x, wid = tid >> 5, lid = tid & 31;
    const int gq = lid >> 2, tg = lid & 3;                  // quad group / thread-in-group
    const int wm = wid >> 2, wn = wid & 3;                  // warps: 2 (m) x 4 (n)
    const int e = blockIdx.z;
    const int m0 = blockIdx.x * 128;
    const int n0 = blockIdx.y * 128;
    const uint32_t sb = s2u(sm);

    const float* gA = X  + ((size_t)e * TOK + m0) * HID;                 // row m, k contig
    const float* gG = Wg + (size_t)e * HID * INTR + n0;                  // row k, n contig
    const float* gU = Wu + (size_t)e * HID * INTR + n0;

    float accg[4][4][4], accu[4][4][4];
#pragma unroll
    for (int i = 0; i < 4; i++)
#pragma unroll
        for (int j = 0; j < 4; j++)
#pragma unroll
            for (int v = 0; v < 4; v++) { accg[i][j][v] = 0.f; accu[i][j][v] = 0.f; }

    const int NT = HID / 32;   // 64
#pragma unroll
    for (int s = 0; s < G1_STAGES - 1; s++) {
        uint32_t base = sb + (uint32_t)(s * G1_STAGE_F) * 4;
        load_A(base, gA + s * 32, HID, tid);
        load_B(base + A_FLOATS * 4,              gG + (size_t)(s * 32) * INTR, INTR, tid);
        load_B(base + (A_FLOATS + B_FLOATS) * 4, gU + (size_t)(s * 32) * INTR, INTR, tid);
        CP_COMMIT();
    }

    for (int kt = 0; kt < NT; kt++) {
        CP_WAIT(G1_STAGES - 2);
        __syncthreads();
        int pf = kt + G1_STAGES - 1;
        if (pf < NT) {
            uint32_t base = sb + (uint32_t)((pf % G1_STAGES) * G1_STAGE_F) * 4;
            load_A(base, gA + pf * 32, HID, tid);
            load_B(base + A_FLOATS * 4,              gG + (size_t)(pf * 32) * INTR, INTR, tid);
            load_B(base + (A_FLOATS + B_FLOATS) * 4, gU + (size_t)(pf * 32) * INTR, INTR, tid);
        }
        CP_COMMIT();

        const float* As = sm + (kt % G1_STAGES) * G1_STAGE_F;
        const float* Bg = As + A_FLOATS;
        const float* Bu = Bg + B_FLOATS;
#pragma unroll
        for (int ks = 0; ks < 4; ks++) {
            const int k0 = ks * 8;
            uint32_t a[4][4];
#pragma unroll
            for (int mt = 0; mt < 4; mt++) {
                int m = wm * 64 + mt * 16 + gq;
                a[mt][0] = f2tf(As[m * A_STRIDE + k0 + tg]);
                a[mt][1] = f2tf(As[(m + 8) * A_STRIDE + k0 + tg]);
                a[mt][2] = f2tf(As[m * A_STRIDE + k0 + tg + 4]);
                a[mt][3] = f2tf(As[(m + 8) * A_STRIDE + k0 + tg + 4]);
            }
            uint32_t bg[4][2], bu[4][2];
#pragma unroll
            for (int nt = 0; nt < 4; nt++) {
                int n = wn * 32 + nt * 8 + gq;
                bg[nt][0] = f2tf(Bg[(k0 + tg) * B_STRIDE + n]);
                bg[nt][1] = f2tf(Bg[(k0 + tg + 4) * B_STRIDE + n]);
                bu[nt][0] = f2tf(Bu[(k0 + tg) * B_STRIDE + n]);
                bu[nt][1] = f2tf(Bu[(k0 + tg + 4) * B_STRIDE + n]);
            }
#pragma unroll
            for (int mt = 0; mt < 4; mt++)
#pragma unroll
                for (int nt = 0; nt < 4; nt++) {
                    mma8(accg[mt][nt], a[mt], bg[nt]);
                    mma8(accu[mt][nt], a[mt], bu[nt]);
                }
        }
    }

    // epilogue: h = up * silu(gate)
    const size_t hb = ((size_t)e * TOK + m0 + wm * 64) * INTR + n0 + wn * 32;
#pragma unroll
    for (int mt = 0; mt < 4; mt++)
#pragma unroll
        for (int nt = 0; nt < 4; nt++) {
            int col = nt * 8 + tg * 2;
            {
                int row = mt * 16 + gq;
                float h0 = accu[mt][nt][0] * silu(accg[mt][nt][0]);
                float h1 = accu[mt][nt][1] * silu(accg[mt][nt][1]);
                *reinterpret_cast<float2*>(&Hout[hb + (size_t)row * INTR + col]) =
                    make_float2(h0, h1);
            }
            {
                int row = mt * 16 + gq + 8;
                float h2 = accu[mt][nt][2] * silu(accg[mt][nt][2]);
                float h3 = accu[mt][nt][3] * silu(accg[mt][nt][3]);
                *reinterpret_cast<float2*>(&Hout[hb + (size_t)row * INTR + col]) =
                    make_float2(h2, h3);
            }
        }
}

// ---------------- GEMM 2: out = h @ down_w ----------------------------------------
__global__ void __launch_bounds__(256, 2)
gemm_down(const float* __restrict__ Hin, const float* __restrict__ Wd,
          float* __restrict__ Out) {
    extern __shared__ float sm[];
    const int tid = threadIdx.x, wid = tid >> 5, lid = tid & 31;
    const int gq = lid >> 2, tg = lid & 3;
    const int wm = wid >> 2, wn = wid & 3;
    const int e = blockIdx.z;
    const int m0 = blockIdx.x * 128;
    const int n0 = blockIdx.y * 128;
    const uint32_t sb = s2u(sm);

    const float* gA = Hin + ((size_t)e * TOK + m0) * INTR;
    const float* gB = Wd  + (size_t)e * INTR * HID + n0;

    float acc[4][4][4];
#pragma unroll
    for (int i = 0; i < 4; i++)
#pragma unroll
        for (int j = 0; j < 4; j++)
#pragma unroll
            for (int v = 0; v < 4; v++) acc[i][j][v] = 0.f;

    const int NT = INTR / 32;   // 256
#pragma unroll
    for (int s = 0; s < G2_STAGES - 1; s++) {
        uint32_t base = sb + (uint32_t)(s * G2_STAGE_F) * 4;
        load_A(base, gA + s * 32, INTR, tid);
        load_B(base + A_FLOATS * 4, gB + (size_t)(s * 32) * HID, HID, tid);
        CP_COMMIT();
    }

    for (int kt = 0; kt < NT; kt++) {
        CP_WAIT(G2_STAGES - 2);
        __syncthreads();
        int pf = kt + G2_STAGES - 1;
        if (pf < NT) {
            uint32_t base = sb + (uint32_t)((pf % G2_STAGES) * G2_STAGE_F) * 4;
            load_A(base, gA + pf * 32, INTR, tid);
            load_B(base + A_FLOATS * 4, gB + (size_t)(pf * 32) * HID, HID, tid);
        }
        CP_COMMIT();

        const float* As = sm + (kt % G2_STAGES) * G2_STAGE_F;
        const float* Bs = As + A_FLOATS;
#pragma unroll
        for (int ks = 0; ks < 4; ks++) {
            const int k0 = ks * 8;
            uint32_t a[4][4];
#pragma unroll
            for (int mt = 0; mt < 4; mt++) {
                int m = wm * 64 + mt * 16 + gq;
                a[mt][0] = f2tf(As[m * A_STRIDE + k0 + tg]);
                a[mt][1] = f2tf(As[(m + 8) * A_STRIDE + k0 + tg]);
                a[mt][2] = f2tf(As[m * A_STRIDE + k0 + tg + 4]);
                a[mt][3] = f2tf(As[(m + 8) * A_STRIDE + k0 + tg + 4]);
            }
            uint32_t b[4][2];
#pragma unroll
            for (int nt = 0; nt < 4; nt++) {
                int n = wn * 32 + nt * 8 + gq;
                b[nt][0] = f2tf(Bs[(k0 + tg) * B_STRIDE + n]);
                b[nt][1] = f2tf(Bs[(k0 + tg + 4) * B_STRIDE + n]);
            }
#pragma unroll
            for (int mt = 0; mt < 4; mt++)
#pragma unroll
                for (int nt = 0; nt < 4; nt++)
                    mma8(acc[mt][nt], a[mt], b[nt]);
        }
    }

    const size_t ob = ((size_t)e * TOK + m0 + wm * 64) * HID + n0 + wn * 32;
#pragma unroll
    for (int mt = 0; mt < 4; mt++)
#pragma unroll
        for (int nt = 0; nt < 4; nt++) {
            int col = nt * 8 + tg * 2;
            int row = mt * 16 + gq;
            *reinterpret_cast<float2*>(&Out[ob + (size_t)row * HID + col]) =
                make_float2(acc[mt][nt][0], acc[mt][nt][1]);
            *reinterpret_cast<float2*>(&Out[ob + (size_t)(row + 8) * HID + col]) =
                make_float2(acc[mt][nt][2], acc[mt][nt][3]);
        }
}

// ---------------- launch ----------------------------------------------------------
extern "C" void kernel_launch(void* const* d_in, const int* in_sizes, int n_in,
                              void* d_out, int out_size) {
    const float* X  = (const float*)d_in[0];
    const float* Wg = (const float*)d_in[1];
    const float* Wu = (const float*)d_in[2];
    const float* Wd = (const float*)d_in[3];
    float* out = (float*)d_out;

    float* hbuf;
    cudaGetSymbolAddress((void**)&hbuf, g_h);

    cudaFuncSetAttribute(gemm_gateup, cudaFuncAttributeMaxDynamicSharedMemorySize, G1_SMEM);
    cudaFuncSetAttribute(gemm_down,   cudaFuncAttributeMaxDynamicSharedMemorySize, G2_SMEM);

    // x = m tiles fastest -> consecutive CTAs share weight strips (L2 reuse)
    gemm_gateup<<<dim3(TOK / 128, INTR / 128, NE), 256, G1_SMEM>>>(X, Wg, Wu, hbuf);
    gemm_down  <<<dim3(TOK / 128, HID / 128, NE), 256, G2_SMEM>>>(hbuf, Wd, out);
}